// round 3
// baseline (speedup 1.0000x reference)
#include <cuda_runtime.h>

typedef unsigned long long u64;

#define HID 16
#define TSEQ 64
#define NB 2048
#define MAX_STEPS 16

// ---------------- packed fp32x2 + MUFU helpers ----------------
__device__ __forceinline__ u64 ffma2(u64 a, u64 b, u64 c) {
    u64 d; asm("fma.rn.f32x2 %0, %1, %2, %3;" : "=l"(d) : "l"(a), "l"(b), "l"(c)); return d;
}
__device__ __forceinline__ u64 fmul2(u64 a, u64 b) {
    u64 d; asm("mul.rn.f32x2 %0, %1, %2;" : "=l"(d) : "l"(a), "l"(b)); return d;
}
__device__ __forceinline__ float2 unpk2(u64 a) {
    float lo, hi; asm("mov.b64 {%0, %1}, %2;" : "=f"(lo), "=f"(hi) : "l"(a));
    return make_float2(lo, hi);
}
__device__ __forceinline__ u64 pk2(float lo, float hi) {
    u64 d; asm("mov.b64 %0, {%1, %2};" : "=l"(d) : "f"(lo), "f"(hi)); return d;
}
__device__ __forceinline__ float ex2a(float x){ float r; asm("ex2.approx.f32 %0, %1;" : "=f"(r) : "f"(x)); return r; }
__device__ __forceinline__ float rcpa(float x){ float r; asm("rcp.approx.f32 %0, %1;" : "=f"(r) : "f"(x)); return r; }
__device__ __forceinline__ float lg2a(float x){ float r; asm("lg2.approx.f32 %0, %1;" : "=f"(r) : "f"(x)); return r; }

// tanh(x) = 1 - 2/(exp(2x)+1)
__device__ __forceinline__ float fast_tanh(float x){
    float e = ex2a(x * 2.885390081777927f);      // 2*log2(e)
    return fmaf(-2.0f, rcpa(e + 1.0f), 1.0f);
}
// sigmoid(x) = 1/(1+exp(-x))
__device__ __forceinline__ float fast_sigmoid(float x){
    float e = ex2a(x * -1.4426950408889634f);    // -log2(e)
    return rcpa(e + 1.0f);
}

// 16-float dot: broadcast vector in smem (16B-aligned) vs register-resident packed weights
__device__ __forceinline__ float dot16s(const float* __restrict__ src, const u64* wp){
    const ulonglong2* v = (const ulonglong2*)src;
    ulonglong2 a0 = v[0], a1 = v[1], a2 = v[2], a3 = v[3];
    u64 s0 = fmul2(a0.x, wp[0]);
    u64 s1 = fmul2(a1.x, wp[2]);
    s0 = ffma2(a0.y, wp[1], s0);
    s1 = ffma2(a1.y, wp[3], s1);
    s0 = ffma2(a2.x, wp[4], s0);
    s1 = ffma2(a3.x, wp[6], s1);
    s0 = ffma2(a2.y, wp[5], s0);
    s1 = ffma2(a3.y, wp[7], s1);
    float2 p = unpk2(s0), q = unpk2(s1);
    return (p.x + p.y) + (q.x + q.y);
}

__device__ __forceinline__ void load_row16(const float* __restrict__ base, u64* wp){
    const float4* p = (const float4*)base;
#pragma unroll
    for (int k = 0; k < 4; ++k) {
        float4 f = p[k];
        wp[2*k]   = pk2(f.x, f.y);
        wp[2*k+1] = pk2(f.z, f.w);
    }
}

// f(v) = w3 @ tanh(w2 @ tanh(w1 @ v + b1) + b2) + b3, component `l`.
// `a` is this thread's component of the argument vector; SA/SB are the
// per-sample broadcast slots (SA banks disjoint from the other sample's SA).
__device__ __forceinline__ float f_eval(float a, float* SA, float* SB, int l,
                                        const u64* w1p, const u64* w2p, const u64* w3p,
                                        float b1v, float b2v, float b3v){
    __syncwarp();                 // previous readers of SA are done
    SA[l] = a;  __syncwarp();
    float h1 = fast_tanh(dot16s(SA, w1p) + b1v);
    SB[l] = h1; __syncwarp();
    float h2 = fast_tanh(dot16s(SB, w2p) + b2v);
    SA[l] = h2; __syncwarp();     // arg already consumed by everyone
    return dot16s(SA, w3p) + b3v;
}

__global__ void __launch_bounds__(32) ode_rnn_kernel(
    const float* __restrict__ x_seq,
    const float* __restrict__ w1, const float* __restrict__ b1,
    const float* __restrict__ w2, const float* __restrict__ b2,
    const float* __restrict__ w3, const float* __restrict__ b3,
    const float* __restrict__ gwih, const float* __restrict__ gwhh,
    const float* __restrict__ gb,  const float* __restrict__ gbn,
    const float* __restrict__ pw,  const float* __restrict__ pb,
    float* __restrict__ out)
{
    const int lane = threadIdx.x;
    const int l = lane & 15;          // hidden component
    const int s = lane >> 4;          // sample within warp (0/1)
    const int b = blockIdx.x * 2 + s;

    // per-sample regions 48 floats apart -> the two samples' active slots live
    // in disjoint bank halves (48 mod 32 == 16), so STS/LDS are conflict-free.
    __shared__ __align__(16) float sbuf[2*48];
    float* SA = sbuf + s * 48;
    float* SB = SA + 16;

    // register-resident weights (rows owned by this thread)
    u64 w1p[8], w2p[8], w3p[8], whr[8], whz[8], whn[8];
    load_row16(w1 + l*16, w1p);
    load_row16(w2 + l*16, w2p);
    load_row16(w3 + l*16, w3p);
    load_row16(gwhh + l*16,        whr);
    load_row16(gwhh + (16+l)*16,   whz);
    load_row16(gwhh + (32+l)*16,   whn);
    const float b1v = b1[l], b2v = b2[l], b3v = b3[l];
    const float wr0 = gwih[l*2],        wr1 = gwih[l*2+1];
    const float wz0 = gwih[(16+l)*2],   wz1 = gwih[(16+l)*2+1];
    const float wn0 = gwih[(32+l)*2],   wn1 = gwih[(32+l)*2+1];
    const float gbr = gb[l], gbz = gb[16+l], gbnn = gb[32+l];
    const float bnv = gbn[l];
    const float pwv = pw[l];
    const float pbv = pb[0];

    float y = 0.0f;
    const float* xb = x_seq + (size_t)b * (TSEQ*2);

#pragma unroll 1
    for (int ts = 0; ts < TSEQ; ++ts) {
        const float x0 = xb[ts*2 + 0];
        const float x1 = xb[ts*2 + 1];

        // ---- adaptive Tsit5, t: 0 -> 1 ----
        float t = 0.0f, dt = 1.0f;
#pragma unroll 1
        for (int it = 0; it < MAX_STEPS; ++it) {
            // exact freeze: dt_c==0 makes the iteration a bit-exact identity
            if (__all_sync(0xffffffffu, t >= 1.0f)) break;
            float dt_c = fminf(dt, 1.0f - t);

            float k1 = f_eval(y, SA, SB, l, w1p, w2p, w3p, b1v, b2v, b3v);
            float a = 0.161f * k1;
            float k2 = f_eval(fmaf(dt_c, a, y), SA, SB, l, w1p, w2p, w3p, b1v, b2v, b3v);
            a = fmaf(0.335480655492357f, k2, -0.008480655492356989f * k1);
            float k3 = f_eval(fmaf(dt_c, a, y), SA, SB, l, w1p, w2p, w3p, b1v, b2v, b3v);
            a = 2.8971530571054935f * k1;
            a = fmaf(-6.359448489975075f, k2, a);
            a = fmaf(4.3622954328695815f, k3, a);
            float k4 = f_eval(fmaf(dt_c, a, y), SA, SB, l, w1p, w2p, w3p, b1v, b2v, b3v);
            a = 5.325864828439257f * k1;
            a = fmaf(-11.748883564062828f, k2, a);
            a = fmaf(7.4955393428898365f, k3, a);
            a = fmaf(-0.09249506636175525f, k4, a);
            float k5 = f_eval(fmaf(dt_c, a, y), SA, SB, l, w1p, w2p, w3p, b1v, b2v, b3v);
            a = 5.86145544294642f * k1;
            a = fmaf(-12.92096931784711f, k2, a);
            a = fmaf(8.159367898576159f, k3, a);
            a = fmaf(-0.071584973281401f, k4, a);
            a = fmaf(-0.028269050394068383f, k5, a);
            float k6 = f_eval(fmaf(dt_c, a, y), SA, SB, l, w1p, w2p, w3p, b1v, b2v, b3v);
            a = 0.09646076681806523f * k1;
            a = fmaf(0.01f, k2, a);
            a = fmaf(0.4798896504144996f, k3, a);
            a = fmaf(1.379008574103742f, k4, a);
            a = fmaf(-3.290069515436081f, k5, a);
            a = fmaf(2.324710524099774f, k6, a);
            float y_new = fmaf(dt_c, a, y);
            float k7 = f_eval(y_new, SA, SB, l, w1p, w2p, w3p, b1v, b2v, b3v);

            a = -0.001780011052225777f * k1;
            a = fmaf(-0.0008164344596567469f, k2, a);
            a = fmaf(0.007880878010261995f, k3, a);
            a = fmaf(-0.1447110071732629f, k4, a);
            a = fmaf(0.5823571654525552f, k5, a);
            a = fmaf(-0.45808210592918697f, k6, a);
            a = fmaf(0.015151515151515152f, k7, a);
            float err = dt_c * a;
            float scale = fmaf(0.01f, fmaxf(fabsf(y), fabsf(y_new)), 0.0001f);
            float q = __fdividef(err, scale);
            float e = q * q;
            e += __shfl_xor_sync(0xffffffffu, e, 8);
            e += __shfl_xor_sync(0xffffffffu, e, 4);
            e += __shfl_xor_sync(0xffffffffu, e, 2);
            e += __shfl_xor_sync(0xffffffffu, e, 1);
            float err2 = fmaxf(e * 0.0625f, 1e-16f);

            bool accept = (err2 <= 1.0f);
            if (accept) { y = y_new; t = t + dt_c; }
            // factor = clip(0.9 * err2^(-0.1), 0.2, 10)
            float factor = fminf(fmaxf(0.9f * ex2a(-0.1f * lg2a(err2)), 0.2f), 10.0f);
            dt = dt_c * factor;
        }

        // ---- GRU update with x_t ----
        __syncwarp();
        SA[l] = y; __syncwarp();
        float hr = dot16s(SA, whr);
        float hz = dot16s(SA, whz);
        float hn = dot16s(SA, whn);
        float ir  = fmaf(x0, wr0, fmaf(x1, wr1, gbr));
        float iz  = fmaf(x0, wz0, fmaf(x1, wz1, gbz));
        float inn = fmaf(x0, wn0, fmaf(x1, wn1, gbnn));
        float r = fast_sigmoid(ir + hr);
        float z = fast_sigmoid(iz + hz);
        float n = fast_tanh(fmaf(r, hn + bnv, inn));
        y = n + z * (y - n);
    }

    // ---- prediction head: out[b] = dot(h, pred_w) + pred_b ----
    float v = y * pwv;
    v += __shfl_xor_sync(0xffffffffu, v, 8);
    v += __shfl_xor_sync(0xffffffffu, v, 4);
    v += __shfl_xor_sync(0xffffffffu, v, 2);
    v += __shfl_xor_sync(0xffffffffu, v, 1);
    if (l == 0) out[b] = v + pbv;
}

extern "C" void kernel_launch(void* const* d_in, const int* in_sizes, int n_in,
                              void* d_out, int out_size) {
    (void)in_sizes; (void)n_in; (void)out_size;
    ode_rnn_kernel<<<NB/2, 32>>>(
        (const float*)d_in[0],  // x_seq
        (const float*)d_in[1],  (const float*)d_in[2],   // w1 b1
        (const float*)d_in[3],  (const float*)d_in[4],   // w2 b2
        (const float*)d_in[5],  (const float*)d_in[6],   // w3 b3
        (const float*)d_in[7],  (const float*)d_in[8],   // gru_wih gru_whh
        (const float*)d_in[9],  (const float*)d_in[10],  // gru_b gru_bn
        (const float*)d_in[11], (const float*)d_in[12],  // pred_w pred_b
        (float*)d_out);
}